// round 12
// baseline (speedup 1.0000x reference)
#include <cuda_runtime.h>
#include <cuda_fp16.h>
#include <math.h>
#include <stdint.h>

// ---------------------------------------------------------------------------
// FusedHybridBlock, all GEMMs fp16 mma.sync.m16n8k16 (f32 accumulate).
// R12 = R10 pipeline (proven best: 3 stages, wait<2>, 2 barriers/k-tile,
// prefetch distance 3) + ONE change: loader address hoisting.
//   chunk c = tid + 256i  =>  mat fixed per i, off = tid&7 const,
//   row = (tid>>3) + 32i, swizzle mask = ((tid>>3)&7)<<4 const
//   => 3 base pointers + 1 swizzled dst offset, strides +4096i / +32i*rs /
//      +kt*128. Cuts the alu-pipe load-address math (R10 ncu: alu 17.1%).
// R11 post-mortem: single-barrier wait<1> pipeline regressed (shorter
// prefetch distance + cp issue colliding with ldsm at barrier release).
// ---------------------------------------------------------------------------

#define NTHREADS   256
#define GTHREADS   256
#define STAGE_A    16384                        // 128 rows x 128B
#define STAGE_B    8192                         // 64 rows x 128B
#define STAGE_BYTES (STAGE_A + 2 * STAGE_B)     // 32768
#define NSTG       3
#define SMEM_BYTES (NSTG * STAGE_BYTES + 1024)  // 99328 -> 2 CTAs/SM

static const int Mdim = 16384;
static const int Ddim = 1024;
static const int Fdim = 4096;
static const int Tdim = 2048;

// -------------------- scratch ----------------------------------------------
__device__ float  g_Aa [16384 * 1024];
__device__ float  g_Bb [16384 * 1024];
__device__ float  g_x1 [16384 * 1024];
__device__ __half g_y1 [16384 * 1024];
__device__ __half g_sp [16384 * 1024];
__device__ __half g_y2 [16384 * 1024];
__device__ __half g_act[16384 * 4096];
__device__ __half g_wh [16 * 1024 * 1024];

// -------------------- helpers ----------------------------------------------
__device__ __forceinline__ float softplusf(float v) {
    return fmaxf(v, 0.f) + log1pf(expf(-fabsf(v)));
}
__device__ __forceinline__ float sigmoidf(float v) {
    return 1.f / (1.f + expf(-v));
}
__device__ __forceinline__ uint32_t smem_u32(const void* p) {
    uint32_t a;
    asm("{ .reg .u64 t; cvta.to.shared.u64 t, %1; cvt.u32.u64 %0, t; }"
        : "=r"(a) : "l"(p));
    return a;
}
#define SWZ(off) ((off) ^ (((off) >> 3) & 0x70))

__device__ __forceinline__ void cp16(uint32_t dst, const void* src) {
    asm volatile("cp.async.cg.shared.global [%0], [%1], 16;" :: "r"(dst), "l"(src));
}
__device__ __forceinline__ void cp_commit() {
    asm volatile("cp.async.commit_group;" ::: "memory");
}
template <int N>
__device__ __forceinline__ void cp_wait() {
    asm volatile("cp.async.wait_group %0;" :: "n"(N) : "memory");
}
__device__ __forceinline__ void ldsm4(uint32_t* r, uint32_t addr) {
    asm volatile("ldmatrix.sync.aligned.m8n8.x4.shared.b16 {%0,%1,%2,%3}, [%4];"
        : "=r"(r[0]), "=r"(r[1]), "=r"(r[2]), "=r"(r[3]) : "r"(addr));
}
__device__ __forceinline__ void mma16h(float* d, const uint32_t* a, const uint32_t* b) {
    asm volatile(
        "mma.sync.aligned.m16n8k16.row.col.f32.f16.f16.f32 "
        "{%0,%1,%2,%3}, {%4,%5,%6,%7}, {%8,%9}, {%0,%1,%2,%3};"
        : "+f"(d[0]), "+f"(d[1]), "+f"(d[2]), "+f"(d[3])
        : "r"(a[0]), "r"(a[1]), "r"(a[2]), "r"(a[3]), "r"(b[0]), "r"(b[1]));
}

// -------------------- batched weight conversion fp32 -> fp16 -----------------
__global__ void w2h4_kernel(const float4* __restrict__ s0, const float4* __restrict__ s1,
                            const float4* __restrict__ s2, const float4* __restrict__ s3,
                            __half2* __restrict__ d0, __half2* __restrict__ d1,
                            __half2* __restrict__ d2, __half2* __restrict__ d3) {
    const int reg = blockIdx.x >> 10;
    const int i   = (blockIdx.x & 1023) * blockDim.x + threadIdx.x;
    const float4* s = (reg == 0) ? s0 : (reg == 1) ? s1 : (reg == 2) ? s2 : s3;
    __half2*      d = (reg == 0) ? d0 : (reg == 1) ? d1 : (reg == 2) ? d2 : d3;
    float4 v = s[i];
    d[2 * i]     = __floats2half2_rn(v.x, v.y);
    d[2 * i + 1] = __floats2half2_rn(v.z, v.w);
}
__global__ void w2h3_kernel(const float4* __restrict__ s0, const float4* __restrict__ s1,
                            const float4* __restrict__ s2,
                            __half2* __restrict__ d0, __half2* __restrict__ d1,
                            __half2* __restrict__ d2) {
    const int reg = blockIdx.x >> 12;
    const int i   = (blockIdx.x & 4095) * blockDim.x + threadIdx.x;
    const float4* s = (reg == 0) ? s0 : (reg == 1) ? s1 : s2;
    __half2*      d = (reg == 0) ? d0 : (reg == 1) ? d1 : d2;
    float4 v = s[i];
    d[2 * i]     = __floats2half2_rn(v.x, v.y);
    d[2 * i + 1] = __floats2half2_rn(v.z, v.w);
}

// -------------------- RMSNorm -> fp16 ----------------------------------------
__global__ void rmsnorm_kernel(const float* __restrict__ x,
                               const float* __restrict__ w,
                               __half* __restrict__ y) {
    const int row = blockIdx.x;
    const int t = threadIdx.x;
    float4 v = ((const float4*)(x + (size_t)row * 1024))[t];
    float ss = v.x * v.x + v.y * v.y + v.z * v.z + v.w * v.w;
    #pragma unroll
    for (int off = 16; off > 0; off >>= 1)
        ss += __shfl_xor_sync(0xffffffffu, ss, off);
    __shared__ float red[8];
    if ((t & 31) == 0) red[t >> 5] = ss;
    __syncthreads();
    float tot = red[0]+red[1]+red[2]+red[3]+red[4]+red[5]+red[6]+red[7];
    float rstd = rsqrtf(tot * (1.f / 1024.f) + 1e-6f);
    float4 wv = ((const float4*)w)[t];
    __half2* o = (__half2*)(y + (size_t)row * 1024);
    o[2 * t]     = __floats2half2_rn(v.x * rstd * wv.x, v.y * rstd * wv.y);
    o[2 * t + 1] = __floats2half2_rn(v.z * rstd * wv.z, v.w * rstd * wv.w);
}

// -------------------- liquid + PLIF scan -> fp16 ------------------------------
__global__ void scan_kernel(const float* __restrict__ Ab,
                            const float* __restrict__ Bb,
                            const float* __restrict__ log_tau,
                            const float* __restrict__ thr,
                            __half* __restrict__ spike_in) {
    const int gid = blockIdx.x * blockDim.x + threadIdx.x;  // 0..8191
    const int d = gid & (Ddim - 1);
    const int b = gid >> 10;
    const float pdec = expf(-expf(-log_tau[d]));
    const float omp  = 1.f - pdec;
    const float th   = thr[d];
    size_t idx = (size_t)b * Tdim * Ddim + d;
    float h = 0.f, v = 0.f;
    #pragma unroll 4
    for (int t = 0; t < Tdim; ++t, idx += Ddim) {
        float a  = Ab[idx];
        float bb = Bb[idx];
        h = tanhf(fmaf(a, h, bb));
        float vpre = fmaf(pdec, v, omp * h);
        float s = (vpre > th) ? 1.f : 0.f;
        v = vpre - s * th;
        spike_in[idx] = __float2half_rn(s + h);
    }
}

// ==================== fp16 fused (dual-)GEMM ================================
// CTA 128(m) x 64(n) [EPI 0/1/2] or 128x128 [EPI 3: acc2 = cols +64].
// 8 warps (256 thr) in 4x2 grid, warp tile 32x32, 2 CTAs/SM.
template <int EPI>
__global__ void __launch_bounds__(NTHREADS, 2)
gemm_h(const __half* __restrict__ A,
       const __half* __restrict__ W1,
       const __half* __restrict__ W2,
       void* __restrict__ out1v,
       void* __restrict__ out2v,
       const float* __restrict__ bias1,
       const float* __restrict__ bias2,
       const float* __restrict__ extra,
       int K, int N) {
    constexpr bool WIDE = (EPI == 3);
    extern __shared__ char smem[];
    const uint32_t stg0 = (smem_u32(smem) + 1023u) & ~1023u;

    const int tid  = threadIdx.x;
    const int warp = tid >> 5;
    const int lane = tid & 31;
    const int wm = warp >> 1;          // 0..3 (32-row tiles)
    const int wn = warp & 1;           // 0..1 (32-col tiles)
    const int bm = blockIdx.y * 128;
    const int bn = blockIdx.x * (WIDE ? 128 : 64);

    const char* Arow = (const char*)(A  + (size_t)bm * K);
    const char* B1   = (const char*)(W1 + (size_t)bn * K);
    const char* B2   = WIDE ? (const char*)(W1 + (size_t)(bn + 64) * K)
                            : (const char*)(W2 + (size_t)bn * K);
    const size_t rs = (size_t)K * 2;

    // ---- hoisted loader addressing -----------------------------------------
    // chunk c = tid + 256*i:  i=0..3 -> A rows (tid>>3)+32i
    //                         i=4..5 -> B1 rows (tid>>3)+32(i-4)
    //                         i=6..7 -> B2 rows (tid>>3)+32(i-6)
    // off = (tid&7)*16 const; swizzle mask ((tid>>3)&7)<<4 const (32i keeps
    // row&7). dst(row) = row*128 + (off ^ mask) = dstbase + 4096*i.
    const int rowbase = tid >> 3;                       // 0..31
    const uint32_t off16 = (uint32_t)(tid & 7) * 16;
    const uint32_t dstbase = (uint32_t)rowbase * 128
                           + (off16 ^ (uint32_t)((rowbase & 7) << 4));
    const char* aSrc  = Arow + (size_t)rowbase * rs + off16;
    const char* b1Src = B1   + (size_t)rowbase * rs + off16;
    const char* b2Src = B2   + (size_t)rowbase * rs + off16;
    const size_t rs32 = 32 * rs;

    auto load_stage = [&](int s, int kt) {
        const uint32_t sb = stg0 + s * STAGE_BYTES + dstbase;
        const size_t ko = (size_t)kt * 128;             // bytes (64 halves)
        #pragma unroll
        for (int i = 0; i < 4; ++i)
            cp16(sb + 4096u * i, aSrc + (size_t)i * rs32 + ko);
        #pragma unroll
        for (int i = 0; i < 2; ++i) {
            cp16(sb + STAGE_A + 4096u * i,           b1Src + (size_t)i * rs32 + ko);
            cp16(sb + STAGE_A + STAGE_B + 4096u * i, b2Src + (size_t)i * rs32 + ko);
        }
        cp_commit();
    };

    float acc1[2][4][4];
    float acc2[2][4][4];
    #pragma unroll
    for (int i = 0; i < 2; ++i)
        #pragma unroll
        for (int j = 0; j < 4; ++j)
            #pragma unroll
            for (int k = 0; k < 4; ++k) { acc1[i][j][k] = 0.f; acc2[i][j][k] = 0.f; }

    const int NK = K / 64;
    load_stage(0, 0);
    load_stage(1, 1);
    load_stage(2, 2);

    const int mi  = lane >> 3;
    const int rin = lane & 7;
    const int a_mrow = wm * 32 + (mi & 1) * 8 + rin;   // + mb*16
    const int a_koff = (mi >> 1) * 16;                 // bytes
    const int b_nrow = wn * 32 + (mi >> 1) * 8 + rin;  // + nbp*16
    const int b_koff = (mi & 1) * 16;

    for (int kt = 0; kt < NK; ++kt) {
        const int s = kt % NSTG;
        const int rem = NK - 1 - kt;
        if (rem >= 2)      cp_wait<2>();
        else if (rem == 1) cp_wait<1>();
        else               cp_wait<0>();
        __syncthreads();

        const uint32_t sA  = stg0 + s * STAGE_BYTES;
        const uint32_t sB1 = sA + STAGE_A;
        const uint32_t sB2 = sA + STAGE_A + STAGE_B;

        #pragma unroll
        for (int ks = 0; ks < 4; ++ks) {
            uint32_t a[2][4];
            #pragma unroll
            for (int mb = 0; mb < 2; ++mb)
                ldsm4(a[mb], sA + SWZ((a_mrow + mb * 16) * 128 + ks * 32 + a_koff));

            uint32_t bf1[4][2], bf2[4][2];
            #pragma unroll
            for (int nbp = 0; nbp < 2; ++nbp) {
                uint32_t t[4];
                ldsm4(t, sB1 + SWZ((b_nrow + nbp * 16) * 128 + ks * 32 + b_koff));
                bf1[2*nbp][0] = t[0]; bf1[2*nbp][1] = t[1];
                bf1[2*nbp+1][0] = t[2]; bf1[2*nbp+1][1] = t[3];
                ldsm4(t, sB2 + SWZ((b_nrow + nbp * 16) * 128 + ks * 32 + b_koff));
                bf2[2*nbp][0] = t[0]; bf2[2*nbp][1] = t[1];
                bf2[2*nbp+1][0] = t[2]; bf2[2*nbp+1][1] = t[3];
            }

            #pragma unroll
            for (int mb = 0; mb < 2; ++mb)
                #pragma unroll
                for (int nb = 0; nb < 4; ++nb) {
                    mma16h(acc1[mb][nb], a[mb], bf1[nb]);
                    mma16h(acc2[mb][nb], a[mb], bf2[nb]);
                }
        }
        // 3 stages: the reload below targets the buffer just consumed; the
        // co-resident CTA fills this barrier's bubble.
        if (kt + 3 < NK) {
            __syncthreads();
            load_stage(s, kt + 3);
        }
    }

    // ------------------------------- epilogue -------------------------------
    const int r_base = bm + wm * 32 + (lane >> 2);
    const int c_base = bn + wn * 32 + (lane & 3) * 2;
    float* out1 = (float*)out1v;
    float* out2 = (float*)out2v;
    __half* out1h = (__half*)out1v;

    #pragma unroll
    for (int mb = 0; mb < 2; ++mb) {
        #pragma unroll
        for (int nb = 0; nb < 4; ++nb) {
            const int r0 = r_base + mb * 16;
            const int r1 = r0 + 8;
            const int cc = c_base + nb * 8;
            const size_t o0 = (size_t)r0 * N + cc;
            const size_t o1 = (size_t)r1 * N + cc;
            const float* d1 = acc1[mb][nb];
            const float* d2 = acc2[mb][nb];

            if (EPI == 0) {
                float b1a = __ldg(bias1 + cc), b1b = __ldg(bias1 + cc + 1);
                float b2a = __ldg(bias2 + cc), b2b = __ldg(bias2 + cc + 1);
                float ea  = expf(__ldg(extra + cc));
                float eb  = expf(__ldg(extra + cc + 1));
                float dl;
                dl = softplusf(d1[0] + b1a); float v00 = expf(-dl * ea);
                float w00 = dl * (d2[0] + b2a);
                dl = softplusf(d1[1] + b1b); float v01 = expf(-dl * eb);
                float w01 = dl * (d2[1] + b2b);
                dl = softplusf(d1[2] + b1a); float v10 = expf(-dl * ea);
                float w10 = dl * (d2[2] + b2a);
                dl = softplusf(d1[3] + b1b); float v11 = expf(-dl * eb);
                float w11 = dl * (d2[3] + b2b);
                *(float2*)(out1 + o0) = make_float2(v00, v01);
                *(float2*)(out1 + o1) = make_float2(v10, v11);
                *(float2*)(out2 + o0) = make_float2(w00, w01);
                *(float2*)(out2 + o1) = make_float2(w10, w11);
            } else if (EPI == 1) {
                float b1a = __ldg(bias1 + cc), b1b = __ldg(bias1 + cc + 1);
                float b2a = __ldg(bias2 + cc), b2b = __ldg(bias2 + cc + 1);
                float2 xa = *(const float2*)(extra + o0);
                float2 xb = *(const float2*)(extra + o1);
                float v00 = xa.x + (d1[0] + b1a) * sigmoidf(d2[0] + b2a);
                float v01 = xa.y + (d1[1] + b1b) * sigmoidf(d2[1] + b2b);
                float v10 = xb.x + (d1[2] + b1a) * sigmoidf(d2[2] + b2a);
                float v11 = xb.y + (d1[3] + b1b) * sigmoidf(d2[3] + b2b);
                *(float2*)(out1 + o0) = make_float2(v00, v01);
                *(float2*)(out1 + o1) = make_float2(v10, v11);
            } else if (EPI == 2) {
                float v00 = d1[0] * sigmoidf(d1[0]) * d2[0];
                float v01 = d1[1] * sigmoidf(d1[1]) * d2[1];
                float v10 = d1[2] * sigmoidf(d1[2]) * d2[2];
                float v11 = d1[3] * sigmoidf(d1[3]) * d2[3];
                *(__half2*)(out1h + o0) = __floats2half2_rn(v00, v01);
                *(__half2*)(out1h + o1) = __floats2half2_rn(v10, v11);
            } else {  // EPI == 3 (WIDE)
                const size_t p0 = o0 + 64, p1 = o1 + 64;
                float2 xa = *(const float2*)(extra + o0);
                float2 xb = *(const float2*)(extra + o1);
                float2 ya = *(const float2*)(extra + p0);
                float2 yb = *(const float2*)(extra + p1);
                *(float2*)(out1 + o0) = make_float2(xa.x + d1[0], xa.y + d1[1]);
                *(float2*)(out1 + o1) = make_float2(xb.x + d1[2], xb.y + d1[3]);
                *(float2*)(out1 + p0) = make_float2(ya.x + d2[0], ya.y + d2[1]);
                *(float2*)(out1 + p1) = make_float2(yb.x + d2[2], yb.y + d2[3]);
            }
        }
    }
}

// ---------------------------------------------------------------------------
extern "C" void kernel_launch(void* const* d_in, const int* in_sizes, int n_in,
                              void* d_out, int out_size) {
    const float* x       = (const float*)d_in[0];
    const float* rms_w1  = (const float*)d_in[1];
    const float* rms_w2  = (const float*)d_in[2];
    const float* delta_w = (const float*)d_in[3];
    const float* delta_b = (const float*)d_in[4];
    const float* b_w     = (const float*)d_in[5];
    const float* b_b     = (const float*)d_in[6];
    const float* A_log   = (const float*)d_in[7];
    const float* log_tau = (const float*)d_in[8];
    const float* plif_thr= (const float*)d_in[9];
    const float* syn_w   = (const float*)d_in[10];
    const float* syn_b   = (const float*)d_in[11];
    const float* gate_w  = (const float*)d_in[12];
    const float* gate_b  = (const float*)d_in[13];
    const float* ffn_g_w = (const float*)d_in[14];
    const float* ffn_u_w = (const float*)d_in[15];
    const float* ffn_d_w = (const float*)d_in[16];
    float* out = (float*)d_out;

    float *Aa, *Bb, *x1;
    __half *y1, *sp, *y2, *act, *wh;
    cudaGetSymbolAddress((void**)&Aa,  g_Aa);
    cudaGetSymbolAddress((void**)&Bb,  g_Bb);
    cudaGetSymbolAddress((void**)&x1,  g_x1);
    cudaGetSymbolAddress((void**)&y1,  g_y1);
    cudaGetSymbolAddress((void**)&sp,  g_sp);
    cudaGetSymbolAddress((void**)&y2,  g_y2);
    cudaGetSymbolAddress((void**)&act, g_act);
    cudaGetSymbolAddress((void**)&wh,  g_wh);

    cudaFuncSetAttribute(gemm_h<0>, cudaFuncAttributeMaxDynamicSharedMemorySize, SMEM_BYTES);
    cudaFuncSetAttribute(gemm_h<1>, cudaFuncAttributeMaxDynamicSharedMemorySize, SMEM_BYTES);
    cudaFuncSetAttribute(gemm_h<2>, cudaFuncAttributeMaxDynamicSharedMemorySize, SMEM_BYTES);
    cudaFuncSetAttribute(gemm_h<3>, cudaFuncAttributeMaxDynamicSharedMemorySize, SMEM_BYTES);

    const int M = Mdim, D = Ddim, F = Fdim;
    const int MEG = 1024 * 1024;

    __half* wh_dw   = wh + 0 * MEG;
    __half* wh_bw   = wh + 1 * MEG;
    __half* wh_syn  = wh + 2 * MEG;
    __half* wh_gate = wh + 3 * MEG;
    __half* wh_g    = wh + 4 * MEG;
    __half* wh_u    = wh + 8 * MEG;
    __half* wh_d    = wh + 12 * MEG;

    w2h4_kernel<<<4096, GTHREADS>>>((const float4*)delta_w, (const float4*)b_w,
                                    (const float4*)syn_w, (const float4*)gate_w,
                                    (__half2*)wh_dw, (__half2*)wh_bw,
                                    (__half2*)wh_syn, (__half2*)wh_gate);
    w2h3_kernel<<<12288, GTHREADS>>>((const float4*)ffn_g_w, (const float4*)ffn_u_w,
                                     (const float4*)ffn_d_w,
                                     (__half2*)wh_g, (__half2*)wh_u, (__half2*)wh_d);

    rmsnorm_kernel<<<M, 256>>>(x, rms_w1, y1);

    dim3 g1(D / 64, M / 128);
    gemm_h<0><<<g1, NTHREADS, SMEM_BYTES>>>(y1, wh_dw, wh_bw, Aa, Bb,
                                            delta_b, b_b, A_log, D, D);
    scan_kernel<<<64, 128>>>(Aa, Bb, log_tau, plif_thr, sp);

    gemm_h<1><<<g1, NTHREADS, SMEM_BYTES>>>(sp, wh_syn, wh_gate, x1, nullptr,
                                            syn_b, gate_b, x, D, D);
    rmsnorm_kernel<<<M, 256>>>(x1, rms_w2, y2);

    dim3 g3(F / 64, M / 128);
    gemm_h<2><<<g3, NTHREADS, SMEM_BYTES>>>(y2, wh_g, wh_u, act, nullptr,
                                            nullptr, nullptr, nullptr, D, F);
    dim3 g4(D / 128, M / 128);
    gemm_h<3><<<g4, NTHREADS, SMEM_BYTES>>>(act, wh_d, nullptr, out, nullptr,
                                            nullptr, nullptr, x1, F, D);
}

// round 13
// speedup vs baseline: 1.0388x; 1.0388x over previous
#include <cuda_runtime.h>
#include <cuda_fp16.h>
#include <math.h>
#include <stdint.h>

// ---------------------------------------------------------------------------
// FusedHybridBlock, all GEMMs fp16 mma.sync.m16n8k16 (f32 accumulate).
// R13 = exact R10 GEMM (proven best: 3 stages, wait<2>, 2 barriers/k-tile;
// R11 single-barrier and R12 hoisted-loader both regressed — the ~62% tensor
// plateau is barrier/dependency bound, not issue bound) + launch fusion:
//   - w2h4 weight conversion rides in rmsnorm1's launch (block range split)
//   - w2h3 rides in the scan's launch (scan uses 32 blocks; w2h3's 12288
//     blocks fill the otherwise-idle SMs -> its ~15us vanishes)
// 9 -> 7 launches; FFN1 (biggest GEMM) lands at ncu capture slot 6.
// ---------------------------------------------------------------------------

#define NTHREADS   256
#define GTHREADS   256
#define STAGE_A    16384                        // 128 rows x 128B
#define STAGE_B    8192                         // 64 rows x 128B
#define STAGE_BYTES (STAGE_A + 2 * STAGE_B)     // 32768
#define NSTG       3
#define SMEM_BYTES (NSTG * STAGE_BYTES + 1024)  // 99328 -> 2 CTAs/SM

static const int Mdim = 16384;
static const int Ddim = 1024;
static const int Fdim = 4096;
static const int Tdim = 2048;

// -------------------- scratch ----------------------------------------------
__device__ float  g_Aa [16384 * 1024];
__device__ float  g_Bb [16384 * 1024];
__device__ float  g_x1 [16384 * 1024];
__device__ __half g_y1 [16384 * 1024];
__device__ __half g_sp [16384 * 1024];
__device__ __half g_y2 [16384 * 1024];
__device__ __half g_act[16384 * 4096];
__device__ __half g_wh [16 * 1024 * 1024];

// -------------------- helpers ----------------------------------------------
__device__ __forceinline__ float softplusf(float v) {
    return fmaxf(v, 0.f) + log1pf(expf(-fabsf(v)));
}
__device__ __forceinline__ float sigmoidf(float v) {
    return 1.f / (1.f + expf(-v));
}
__device__ __forceinline__ uint32_t smem_u32(const void* p) {
    uint32_t a;
    asm("{ .reg .u64 t; cvta.to.shared.u64 t, %1; cvt.u32.u64 %0, t; }"
        : "=r"(a) : "l"(p));
    return a;
}
#define SWZ(off) ((off) ^ (((off) >> 3) & 0x70))

__device__ __forceinline__ void cp16(uint32_t dst, const void* src) {
    asm volatile("cp.async.cg.shared.global [%0], [%1], 16;" :: "r"(dst), "l"(src));
}
__device__ __forceinline__ void cp_commit() {
    asm volatile("cp.async.commit_group;" ::: "memory");
}
template <int N>
__device__ __forceinline__ void cp_wait() {
    asm volatile("cp.async.wait_group %0;" :: "n"(N) : "memory");
}
__device__ __forceinline__ void ldsm4(uint32_t* r, uint32_t addr) {
    asm volatile("ldmatrix.sync.aligned.m8n8.x4.shared.b16 {%0,%1,%2,%3}, [%4];"
        : "=r"(r[0]), "=r"(r[1]), "=r"(r[2]), "=r"(r[3]) : "r"(addr));
}
__device__ __forceinline__ void mma16h(float* d, const uint32_t* a, const uint32_t* b) {
    asm volatile(
        "mma.sync.aligned.m16n8k16.row.col.f32.f16.f16.f32 "
        "{%0,%1,%2,%3}, {%4,%5,%6,%7}, {%8,%9}, {%0,%1,%2,%3};"
        : "+f"(d[0]), "+f"(d[1]), "+f"(d[2]), "+f"(d[3])
        : "r"(a[0]), "r"(a[1]), "r"(a[2]), "r"(a[3]), "r"(b[0]), "r"(b[1]));
}

// -------------------- fused rmsnorm1 + w2h of 4 small weights ----------------
// blocks [0, M): rmsnorm row = blockIdx.x
// blocks [M, M+4096): convert 4 regions of 1M floats (1024 blocks each)
__global__ void rms1_w2h4_kernel(const float* __restrict__ x,
                                 const float* __restrict__ w,
                                 __half* __restrict__ y,
                                 const float4* __restrict__ s0, const float4* __restrict__ s1,
                                 const float4* __restrict__ s2, const float4* __restrict__ s3,
                                 __half2* __restrict__ d0, __half2* __restrict__ d1,
                                 __half2* __restrict__ d2, __half2* __restrict__ d3) {
    const int bid = blockIdx.x;
    const int t = threadIdx.x;
    if (bid < Mdim) {
        float4 v = ((const float4*)(x + (size_t)bid * 1024))[t];
        float ss = v.x * v.x + v.y * v.y + v.z * v.z + v.w * v.w;
        #pragma unroll
        for (int off = 16; off > 0; off >>= 1)
            ss += __shfl_xor_sync(0xffffffffu, ss, off);
        __shared__ float red[8];
        if ((t & 31) == 0) red[t >> 5] = ss;
        __syncthreads();
        float tot = red[0]+red[1]+red[2]+red[3]+red[4]+red[5]+red[6]+red[7];
        float rstd = rsqrtf(tot * (1.f / 1024.f) + 1e-6f);
        float4 wv = ((const float4*)w)[t];
        __half2* o = (__half2*)(y + (size_t)bid * 1024);
        o[2 * t]     = __floats2half2_rn(v.x * rstd * wv.x, v.y * rstd * wv.y);
        o[2 * t + 1] = __floats2half2_rn(v.z * rstd * wv.z, v.w * rstd * wv.w);
    } else {
        const int cb = bid - Mdim;
        const int reg = cb >> 10;
        const int i   = (cb & 1023) * 256 + t;
        const float4* s = (reg == 0) ? s0 : (reg == 1) ? s1 : (reg == 2) ? s2 : s3;
        __half2*      d = (reg == 0) ? d0 : (reg == 1) ? d1 : (reg == 2) ? d2 : d3;
        float4 v = s[i];
        d[2 * i]     = __floats2half2_rn(v.x, v.y);
        d[2 * i + 1] = __floats2half2_rn(v.z, v.w);
    }
}

// -------------------- plain RMSNorm -> fp16 (for y2) --------------------------
__global__ void rmsnorm_kernel(const float* __restrict__ x,
                               const float* __restrict__ w,
                               __half* __restrict__ y) {
    const int row = blockIdx.x;
    const int t = threadIdx.x;
    float4 v = ((const float4*)(x + (size_t)row * 1024))[t];
    float ss = v.x * v.x + v.y * v.y + v.z * v.z + v.w * v.w;
    #pragma unroll
    for (int off = 16; off > 0; off >>= 1)
        ss += __shfl_xor_sync(0xffffffffu, ss, off);
    __shared__ float red[8];
    if ((t & 31) == 0) red[t >> 5] = ss;
    __syncthreads();
    float tot = red[0]+red[1]+red[2]+red[3]+red[4]+red[5]+red[6]+red[7];
    float rstd = rsqrtf(tot * (1.f / 1024.f) + 1e-6f);
    float4 wv = ((const float4*)w)[t];
    __half2* o = (__half2*)(y + (size_t)row * 1024);
    o[2 * t]     = __floats2half2_rn(v.x * rstd * wv.x, v.y * rstd * wv.y);
    o[2 * t + 1] = __floats2half2_rn(v.z * rstd * wv.z, v.w * rstd * wv.w);
}

// -------------------- fused scan + w2h of 3 FFN weights ----------------------
// blocks [0, 32): scan channels gid = bid*256+tid (0..8191)
// blocks [32, 32+12288): convert 3 regions of 4M floats (4096 blocks each)
__global__ void scan_w2h3_kernel(const float* __restrict__ Ab,
                                 const float* __restrict__ Bb,
                                 const float* __restrict__ log_tau,
                                 const float* __restrict__ thr,
                                 __half* __restrict__ spike_in,
                                 const float4* __restrict__ s0, const float4* __restrict__ s1,
                                 const float4* __restrict__ s2,
                                 __half2* __restrict__ d0, __half2* __restrict__ d1,
                                 __half2* __restrict__ d2) {
    const int bid = blockIdx.x;
    const int t = threadIdx.x;
    if (bid < 32) {
        const int gid = bid * 256 + t;          // 0..8191
        const int d = gid & (Ddim - 1);
        const int b = gid >> 10;
        const float pdec = expf(-expf(-log_tau[d]));
        const float omp  = 1.f - pdec;
        const float th   = thr[d];
        size_t idx = (size_t)b * Tdim * Ddim + d;
        float h = 0.f, v = 0.f;
        #pragma unroll 4
        for (int tt = 0; tt < Tdim; ++tt, idx += Ddim) {
            float a  = Ab[idx];
            float bb = Bb[idx];
            h = tanhf(fmaf(a, h, bb));
            float vpre = fmaf(pdec, v, omp * h);
            float s = (vpre > th) ? 1.f : 0.f;
            v = vpre - s * th;
            spike_in[idx] = __float2half_rn(s + h);
        }
    } else {
        const int cb = bid - 32;
        const int reg = cb >> 12;
        const int i   = (cb & 4095) * 256 + t;
        const float4* s = (reg == 0) ? s0 : (reg == 1) ? s1 : s2;
        __half2*      d = (reg == 0) ? d0 : (reg == 1) ? d1 : d2;
        float4 v = s[i];
        d[2 * i]     = __floats2half2_rn(v.x, v.y);
        d[2 * i + 1] = __floats2half2_rn(v.z, v.w);
    }
}

// ==================== fp16 fused (dual-)GEMM (exact R10) =====================
// CTA 128(m) x 64(n) [EPI 0/1/2] or 128x128 [EPI 3: acc2 = cols +64].
// 8 warps (256 thr) in 4x2 grid, warp tile 32x32, 2 CTAs/SM.
template <int EPI>
__global__ void __launch_bounds__(NTHREADS, 2)
gemm_h(const __half* __restrict__ A,
       const __half* __restrict__ W1,
       const __half* __restrict__ W2,
       void* __restrict__ out1v,
       void* __restrict__ out2v,
       const float* __restrict__ bias1,
       const float* __restrict__ bias2,
       const float* __restrict__ extra,
       int K, int N) {
    constexpr bool WIDE = (EPI == 3);
    extern __shared__ char smem[];
    const uint32_t stg0 = (smem_u32(smem) + 1023u) & ~1023u;

    const int tid  = threadIdx.x;
    const int warp = tid >> 5;
    const int lane = tid & 31;
    const int wm = warp >> 1;          // 0..3 (32-row tiles)
    const int wn = warp & 1;           // 0..1 (32-col tiles)
    const int bm = blockIdx.y * 128;
    const int bn = blockIdx.x * (WIDE ? 128 : 64);

    const char* Arow = (const char*)(A  + (size_t)bm * K);
    const char* B1   = (const char*)(W1 + (size_t)bn * K);
    const char* B2   = WIDE ? (const char*)(W1 + (size_t)(bn + 64) * K)
                            : (const char*)(W2 + (size_t)bn * K);
    const size_t rs = (size_t)K * 2;

    // chunks: A=1024 (128 rows x 8), B1=512, B2=512 (64 rows x 8) = 2048
    auto load_stage = [&](int s, int kt) {
        const uint32_t sb = stg0 + s * STAGE_BYTES;
        const size_t ko = (size_t)kt * 128;        // bytes (64 halves)
        #pragma unroll
        for (int i = 0; i < 8; ++i) {
            const int c = tid + i * NTHREADS;
            const char* src;
            uint32_t dst;
            if (c < 1024) {
                const int row = c >> 3, off = c & 7;
                src = Arow + row * rs + ko + off * 16;
                dst = sb + SWZ(row * 128 + off * 16);
            } else if (c < 1536) {
                const int idx = c - 1024;
                const int row = idx >> 3, off = idx & 7;
                src = B1 + row * rs + ko + off * 16;
                dst = sb + STAGE_A + SWZ(row * 128 + off * 16);
            } else {
                const int idx = c - 1536;
                const int row = idx >> 3, off = idx & 7;
                src = B2 + row * rs + ko + off * 16;
                dst = sb + STAGE_A + STAGE_B + SWZ(row * 128 + off * 16);
            }
            cp16(dst, src);
        }
        cp_commit();
    };

    float acc1[2][4][4];
    float acc2[2][4][4];
    #pragma unroll
    for (int i = 0; i < 2; ++i)
        #pragma unroll
        for (int j = 0; j < 4; ++j)
            #pragma unroll
            for (int k = 0; k < 4; ++k) { acc1[i][j][k] = 0.f; acc2[i][j][k] = 0.f; }

    const int NK = K / 64;
    load_stage(0, 0);
    load_stage(1, 1);
    load_stage(2, 2);

    const int mi  = lane >> 3;
    const int rin = lane & 7;
    const int a_mrow = wm * 32 + (mi & 1) * 8 + rin;   // + mb*16
    const int a_koff = (mi >> 1) * 16;                 // bytes
    const int b_nrow = wn * 32 + (mi >> 1) * 8 + rin;  // + nbp*16
    const int b_koff = (mi & 1) * 16;

    for (int kt = 0; kt < NK; ++kt) {
        const int s = kt % NSTG;
        const int rem = NK - 1 - kt;
        if (rem >= 2)      cp_wait<2>();
        else if (rem == 1) cp_wait<1>();
        else               cp_wait<0>();
        __syncthreads();

        const uint32_t sA  = stg0 + s * STAGE_BYTES;
        const uint32_t sB1 = sA + STAGE_A;
        const uint32_t sB2 = sA + STAGE_A + STAGE_B;

        #pragma unroll
        for (int ks = 0; ks < 4; ++ks) {
            uint32_t a[2][4];
            #pragma unroll
            for (int mb = 0; mb < 2; ++mb)
                ldsm4(a[mb], sA + SWZ((a_mrow + mb * 16) * 128 + ks * 32 + a_koff));

            uint32_t bf1[4][2], bf2[4][2];
            #pragma unroll
            for (int nbp = 0; nbp < 2; ++nbp) {
                uint32_t t[4];
                ldsm4(t, sB1 + SWZ((b_nrow + nbp * 16) * 128 + ks * 32 + b_koff));
                bf1[2*nbp][0] = t[0]; bf1[2*nbp][1] = t[1];
                bf1[2*nbp+1][0] = t[2]; bf1[2*nbp+1][1] = t[3];
                ldsm4(t, sB2 + SWZ((b_nrow + nbp * 16) * 128 + ks * 32 + b_koff));
                bf2[2*nbp][0] = t[0]; bf2[2*nbp][1] = t[1];
                bf2[2*nbp+1][0] = t[2]; bf2[2*nbp+1][1] = t[3];
            }

            #pragma unroll
            for (int mb = 0; mb < 2; ++mb)
                #pragma unroll
                for (int nb = 0; nb < 4; ++nb) {
                    mma16h(acc1[mb][nb], a[mb], bf1[nb]);
                    mma16h(acc2[mb][nb], a[mb], bf2[nb]);
                }
        }
        // 3 stages: the reload below targets the buffer just consumed; the
        // co-resident CTA fills this barrier's bubble.
        if (kt + 3 < NK) {
            __syncthreads();
            load_stage(s, kt + 3);
        }
    }

    // ------------------------------- epilogue -------------------------------
    const int r_base = bm + wm * 32 + (lane >> 2);
    const int c_base = bn + wn * 32 + (lane & 3) * 2;
    float* out1 = (float*)out1v;
    float* out2 = (float*)out2v;
    __half* out1h = (__half*)out1v;

    #pragma unroll
    for (int mb = 0; mb < 2; ++mb) {
        #pragma unroll
        for (int nb = 0; nb < 4; ++nb) {
            const int r0 = r_base + mb * 16;
            const int r1 = r0 + 8;
            const int cc = c_base + nb * 8;
            const size_t o0 = (size_t)r0 * N + cc;
            const size_t o1 = (size_t)r1 * N + cc;
            const float* d1 = acc1[mb][nb];
            const float* d2 = acc2[mb][nb];

            if (EPI == 0) {
                float b1a = __ldg(bias1 + cc), b1b = __ldg(bias1 + cc + 1);
                float b2a = __ldg(bias2 + cc), b2b = __ldg(bias2 + cc + 1);
                float ea  = expf(__ldg(extra + cc));
                float eb  = expf(__ldg(extra + cc + 1));
                float dl;
                dl = softplusf(d1[0] + b1a); float v00 = expf(-dl * ea);
                float w00 = dl * (d2[0] + b2a);
                dl = softplusf(d1[1] + b1b); float v01 = expf(-dl * eb);
                float w01 = dl * (d2[1] + b2b);
                dl = softplusf(d1[2] + b1a); float v10 = expf(-dl * ea);
                float w10 = dl * (d2[2] + b2a);
                dl = softplusf(d1[3] + b1b); float v11 = expf(-dl * eb);
                float w11 = dl * (d2[3] + b2b);
                *(float2*)(out1 + o0) = make_float2(v00, v01);
                *(float2*)(out1 + o1) = make_float2(v10, v11);
                *(float2*)(out2 + o0) = make_float2(w00, w01);
                *(float2*)(out2 + o1) = make_float2(w10, w11);
            } else if (EPI == 1) {
                float b1a = __ldg(bias1 + cc), b1b = __ldg(bias1 + cc + 1);
                float b2a = __ldg(bias2 + cc), b2b = __ldg(bias2 + cc + 1);
                float2 xa = *(const float2*)(extra + o0);
                float2 xb = *(const float2*)(extra + o1);
                float v00 = xa.x + (d1[0] + b1a) * sigmoidf(d2[0] + b2a);
                float v01 = xa.y + (d1[1] + b1b) * sigmoidf(d2[1] + b2b);
                float v10 = xb.x + (d1[2] + b1a) * sigmoidf(d2[2] + b2a);
                float v11 = xb.y + (d1[3] + b1b) * sigmoidf(d2[3] + b2b);
                *(float2*)(out1 + o0) = make_float2(v00, v01);
                *(float2*)(out1 + o1) = make_float2(v10, v11);
            } else if (EPI == 2) {
                float v00 = d1[0] * sigmoidf(d1[0]) * d2[0];
                float v01 = d1[1] * sigmoidf(d1[1]) * d2[1];
                float v10 = d1[2] * sigmoidf(d1[2]) * d2[2];
                float v11 = d1[3] * sigmoidf(d1[3]) * d2[3];
                *(__half2*)(out1h + o0) = __floats2half2_rn(v00, v01);
                *(__half2*)(out1h + o1) = __floats2half2_rn(v10, v11);
            } else {  // EPI == 3 (WIDE)
                const size_t p0 = o0 + 64, p1 = o1 + 64;
                float2 xa = *(const float2*)(extra + o0);
                float2 xb = *(const float2*)(extra + o1);
                float2 ya = *(const float2*)(extra + p0);
                float2 yb = *(const float2*)(extra + p1);
                *(float2*)(out1 + o0) = make_float2(xa.x + d1[0], xa.y + d1[1]);
                *(float2*)(out1 + o1) = make_float2(xb.x + d1[2], xb.y + d1[3]);
                *(float2*)(out1 + p0) = make_float2(ya.x + d2[0], ya.y + d2[1]);
                *(float2*)(out1 + p1) = make_float2(yb.x + d2[2], yb.y + d2[3]);
            }
        }
    }
}

// ---------------------------------------------------------------------------
extern "C" void kernel_launch(void* const* d_in, const int* in_sizes, int n_in,
                              void* d_out, int out_size) {
    const float* x       = (const float*)d_in[0];
    const float* rms_w1  = (const float*)d_in[1];
    const float* rms_w2  = (const float*)d_in[2];
    const float* delta_w = (const float*)d_in[3];
    const float* delta_b = (const float*)d_in[4];
    const float* b_w     = (const float*)d_in[5];
    const float* b_b     = (const float*)d_in[6];
    const float* A_log   = (const float*)d_in[7];
    const float* log_tau = (const float*)d_in[8];
    const float* plif_thr= (const float*)d_in[9];
    const float* syn_w   = (const float*)d_in[10];
    const float* syn_b   = (const float*)d_in[11];
    const float* gate_w  = (const float*)d_in[12];
    const float* gate_b  = (const float*)d_in[13];
    const float* ffn_g_w = (const float*)d_in[14];
    const float* ffn_u_w = (const float*)d_in[15];
    const float* ffn_d_w = (const float*)d_in[16];
    float* out = (float*)d_out;

    float *Aa, *Bb, *x1;
    __half *y1, *sp, *y2, *act, *wh;
    cudaGetSymbolAddress((void**)&Aa,  g_Aa);
    cudaGetSymbolAddress((void**)&Bb,  g_Bb);
    cudaGetSymbolAddress((void**)&x1,  g_x1);
    cudaGetSymbolAddress((void**)&y1,  g_y1);
    cudaGetSymbolAddress((void**)&sp,  g_sp);
    cudaGetSymbolAddress((void**)&y2,  g_y2);
    cudaGetSymbolAddress((void**)&act, g_act);
    cudaGetSymbolAddress((void**)&wh,  g_wh);

    cudaFuncSetAttribute(gemm_h<0>, cudaFuncAttributeMaxDynamicSharedMemorySize, SMEM_BYTES);
    cudaFuncSetAttribute(gemm_h<1>, cudaFuncAttributeMaxDynamicSharedMemorySize, SMEM_BYTES);
    cudaFuncSetAttribute(gemm_h<2>, cudaFuncAttributeMaxDynamicSharedMemorySize, SMEM_BYTES);
    cudaFuncSetAttribute(gemm_h<3>, cudaFuncAttributeMaxDynamicSharedMemorySize, SMEM_BYTES);

    const int M = Mdim, D = Ddim, F = Fdim;
    const int MEG = 1024 * 1024;

    __half* wh_dw   = wh + 0 * MEG;
    __half* wh_bw   = wh + 1 * MEG;
    __half* wh_syn  = wh + 2 * MEG;
    __half* wh_gate = wh + 3 * MEG;
    __half* wh_g    = wh + 4 * MEG;
    __half* wh_u    = wh + 8 * MEG;
    __half* wh_d    = wh + 12 * MEG;

    // launch 1: rmsnorm1 + w2h of the four DxD weights (fused, block-split)
    rms1_w2h4_kernel<<<M + 4096, GTHREADS>>>(
        x, rms_w1, y1,
        (const float4*)delta_w, (const float4*)b_w,
        (const float4*)syn_w, (const float4*)gate_w,
        (__half2*)wh_dw, (__half2*)wh_bw, (__half2*)wh_syn, (__half2*)wh_gate);

    // launch 2: A, bvec (dual fp16 GEMM, fused softplus/exp epilogue)
    dim3 g1(D / 64, M / 128);
    gemm_h<0><<<g1, NTHREADS, SMEM_BYTES>>>(y1, wh_dw, wh_bw, Aa, Bb,
                                            delta_b, b_b, A_log, D, D);
    // launch 3: scan + w2h of the three FFN weights (fused; scan uses 32
    // blocks, w2h3's 12288 blocks fill the idle SMs)
    scan_w2h3_kernel<<<32 + 12288, GTHREADS>>>(
        Aa, Bb, log_tau, plif_thr, sp,
        (const float4*)ffn_g_w, (const float4*)ffn_u_w, (const float4*)ffn_d_w,
        (__half2*)wh_g, (__half2*)wh_u, (__half2*)wh_d);

    // launch 4: x1 = x + syn*sigmoid(gate)
    gemm_h<1><<<g1, NTHREADS, SMEM_BYTES>>>(sp, wh_syn, wh_gate, x1, nullptr,
                                            syn_b, gate_b, x, D, D);
    // launch 5: y2 = rmsnorm(x1)
    rmsnorm_kernel<<<M, 256>>>(x1, rms_w2, y2);

    // launch 6 (ncu capture): act = silu(y2@g^T)*(y2@u^T)
    dim3 g3(F / 64, M / 128);
    gemm_h<2><<<g3, NTHREADS, SMEM_BYTES>>>(y2, wh_g, wh_u, act, nullptr,
                                            nullptr, nullptr, nullptr, D, F);
    // launch 7: out = x1 + act@d^T  (WIDE 128-col CTAs)
    dim3 g4(D / 128, M / 128);
    gemm_h<3><<<g4, NTHREADS, SMEM_BYTES>>>(act, wh_d, nullptr, out, nullptr,
                                            nullptr, nullptr, x1, F, D);
}